// round 9
// baseline (speedup 1.0000x reference)
#include <cuda_runtime.h>
#include <cuda_bf16.h>
#include <cstdint>

#define Bsz 2
#define Lq 4096
#define Dm 512
#define Hh 8
#define Ee 64
#define NC 32
#define CS 128
#define BHn (Bsz*Hh)

// ---------------- scratch ----------------------------------------------------
__device__ float g_loglam[BHn * Lq];
__device__ float g_cum[BHn * Lq];
__device__ float g_q[BHn * Lq * Ee];
__device__ float g_k[BHn * Lq * Ee];
__device__ float g_v[BHn * Lq * Ee];
__device__ float g_S[BHn * NC * Ee * Ee];
__device__ float g_z[BHn * NC * Ee];
__device__ float g_out2[Bsz * Lq * Dm];
__device__ __align__(16) __nv_bfloat16 g_xhi[Bsz * Lq * Dm];
__device__ __align__(16) __nv_bfloat16 g_xlo[Bsz * Lq * Dm];
__device__ __align__(16) __nv_bfloat16 g_ahi[Bsz * Lq * Dm];
__device__ __align__(16) __nv_bfloat16 g_alo[Bsz * Lq * Dm];
__device__ __align__(16) __nv_bfloat16 g_wq_hi[3 * Dm * Dm];
__device__ __align__(16) __nv_bfloat16 g_wq_lo[3 * Dm * Dm];
__device__ __align__(16) __nv_bfloat16 g_wo_hi[Dm * Dm];
__device__ __align__(16) __nv_bfloat16 g_wo_lo[Dm * Dm];

// ---------------- low-level helpers -------------------------------------------
__device__ __forceinline__ uint32_t smem_u32(const void* p) {
    uint32_t a;
    asm("{ .reg .u64 t; cvta.to.shared.u64 t, %1; cvt.u32.u64 %0, t; }" : "=r"(a) : "l"(p));
    return a;
}
__device__ __forceinline__ void ldsm4(uint32_t* r, uint32_t addr) {
    asm volatile("ldmatrix.sync.aligned.m8n8.x4.shared.b16 {%0,%1,%2,%3}, [%4];"
                 : "=r"(r[0]), "=r"(r[1]), "=r"(r[2]), "=r"(r[3]) : "r"(addr));
}
__device__ __forceinline__ void mma16816(float* d, const uint32_t* a, const uint32_t* b) {
    asm volatile("mma.sync.aligned.m16n8k16.row.col.f32.bf16.bf16.f32 "
                 "{%0,%1,%2,%3}, {%4,%5,%6,%7}, {%8,%9}, {%0,%1,%2,%3};"
                 : "+f"(d[0]), "+f"(d[1]), "+f"(d[2]), "+f"(d[3])
                 : "r"(a[0]), "r"(a[1]), "r"(a[2]), "r"(a[3]), "r"(b[0]), "r"(b[1]));
}
#define CP_ASYNC16(sm, gm) \
    asm volatile("cp.async.cg.shared.global [%0], [%1], 16;" :: "r"(sm), "l"(gm))
#define CP_COMMIT() asm volatile("cp.async.commit_group;" ::: "memory")
#define CP_WAIT(n)  asm volatile("cp.async.wait_group %0;" :: "n"(n) : "memory")

__device__ __forceinline__ void split2(float v0, float v1,
                                       __nv_bfloat162& ph, __nv_bfloat162& pl) {
    __nv_bfloat16 h0 = __float2bfloat16(v0), h1 = __float2bfloat16(v1);
    ph.x = h0; ph.y = h1;
    pl.x = __float2bfloat16(v0 - __bfloat162float(h0));
    pl.y = __float2bfloat16(v1 - __bfloat162float(h1));
}

// ---------------- K0: fused x split + decay logits (one pass over x) ---------
__global__ __launch_bounds__(256) void split_x_decay_kernel(const float* __restrict__ x,
                                                            const float* __restrict__ dw,
                                                            const float* __restrict__ db) {
    int warp = (blockIdx.x * blockDim.x + threadIdx.x) >> 5;
    int lane = threadIdx.x & 31;
    const float4* xr = (const float4*)(x + (size_t)warp * Dm);
    float4 xv[4];
#pragma unroll
    for (int i = 0; i < 4; i++) xv[i] = xr[lane + 32 * i];
    __nv_bfloat162* hi = (__nv_bfloat162*)(g_xhi + (size_t)warp * Dm);
    __nv_bfloat162* lo = (__nv_bfloat162*)(g_xlo + (size_t)warp * Dm);
#pragma unroll
    for (int i = 0; i < 4; i++) {
        int idx = lane + 32 * i;
        __nv_bfloat162 ph0, pl0, ph1, pl1;
        split2(xv[i].x, xv[i].y, ph0, pl0);
        split2(xv[i].z, xv[i].w, ph1, pl1);
        hi[2 * idx] = ph0; hi[2 * idx + 1] = ph1;
        lo[2 * idx] = pl0; lo[2 * idx + 1] = pl1;
    }
    int b = warp >> 12, l = warp & 4095;
#pragma unroll
    for (int h = 0; h < Hh; h++) {
        const float4* wr = (const float4*)(dw + (size_t)h * Dm);
        float p = 0.f;
#pragma unroll
        for (int i = 0; i < 4; i++) {
            float4 w = wr[lane + 32 * i];
            p += xv[i].x * w.x + xv[i].y * w.y + xv[i].z * w.z + xv[i].w * w.w;
        }
#pragma unroll
        for (int o = 16; o; o >>= 1) p += __shfl_xor_sync(0xffffffffu, p, o);
        if (lane == 0) {
            float logit = p + db[h];
            float lam = 0.9f + 0.1f / (1.f + expf(-logit));
            lam = fmaxf(lam, 1e-6f);
            g_loglam[((size_t)(b * Hh + h)) * Lq + l] = logf(lam);
        }
    }
}

// ---------------- K0w: both weight splits in one launch ----------------------
__global__ void split_w_kernel(const float* __restrict__ qkv_w,
                               const float* __restrict__ out_w) {
    int i = blockIdx.x * blockDim.x + threadIdx.x;
    const int nq = 3 * Dm * Dm / 4;
    const float* s; __nv_bfloat16 *hi, *lo; int j;
    if (i < nq) { s = qkv_w; hi = g_wq_hi; lo = g_wq_lo; j = i; }
    else {
        j = i - nq;
        if (j >= Dm * Dm / 4) return;
        s = out_w; hi = g_wo_hi; lo = g_wo_lo;
    }
    float4 v = ((const float4*)s)[j];
    __nv_bfloat162 ph0, pl0, ph1, pl1;
    split2(v.x, v.y, ph0, pl0);
    split2(v.z, v.w, ph1, pl1);
    ((__nv_bfloat162*)hi)[2 * j] = ph0; ((__nv_bfloat162*)hi)[2 * j + 1] = ph1;
    ((__nv_bfloat162*)lo)[2 * j] = pl0; ((__nv_bfloat162*)lo)[2 * j + 1] = pl1;
}

// ---------------- K0b: inclusive scan of log lambda per (b,h), clip ----------
__global__ void cum_scan_kernel() {
    int bh = blockIdx.x;
    int tid = threadIdx.x;
    int lane = tid & 31, w = tid >> 5;
    const float* src = g_loglam + (size_t)bh * Lq + tid * 8;
    float v[8]; float s = 0.f;
#pragma unroll
    for (int j = 0; j < 8; j++) { v[j] = src[j]; s += v[j]; }
    float sc = s;
#pragma unroll
    for (int o = 1; o < 32; o <<= 1) {
        float n = __shfl_up_sync(0xffffffffu, sc, o);
        if (lane >= o) sc += n;
    }
    __shared__ float wt[16];
    if (lane == 31) wt[w] = sc;
    __syncthreads();
    if (tid < 16) {
        float ws = wt[tid];
#pragma unroll
        for (int o = 1; o < 16; o <<= 1) {
            float n = __shfl_up_sync(0xffffu, ws, o);
            if (tid >= o) ws += n;
        }
        wt[tid] = ws;
    }
    __syncthreads();
    float base = ((w > 0) ? wt[w - 1] : 0.f) + sc - s;
    float run = base;
    float* dst = g_cum + (size_t)bh * Lq + tid * 8;
#pragma unroll
    for (int j = 0; j < 8; j++) {
        run += v[j];
        dst[j] = fminf(fmaxf(run, -50.f), 50.f);
    }
}

// ---------------- HMMA GEMM (bf16x3 split), 128x64 tile, occupancy 3 ---------
template <int EPI>
__global__ __launch_bounds__(256, 3) void gemm_mma_kernel(const float* __restrict__ bias) {
    extern __shared__ __align__(16) char dynsmem[];
    constexpr int KD = 512, BK = 32, NKB = KD / BK;
    constexpr int AOFF = 0, ALOFF = 8192, WOFF = 16384, WLOFF = 20480;
    constexpr int STAGEB = 24576;
    uint32_t sb0 = smem_u32(dynsmem);

    int tid = threadIdx.x;
    int warp = tid >> 5, lane = tid & 31;
    int warp_m = warp & 3, warp_n = warp >> 2;
    int m0 = blockIdx.y * 128, n0 = blockIdx.x * 64;

    const __nv_bfloat16* Ah = (EPI ? g_xhi : g_ahi) + (size_t)m0 * KD;
    const __nv_bfloat16* Al = (EPI ? g_xlo : g_alo) + (size_t)m0 * KD;
    const __nv_bfloat16* Wh = (EPI ? g_wq_hi : g_wo_hi) + (size_t)n0 * KD;
    const __nv_bfloat16* Wl = (EPI ? g_wq_lo : g_wo_lo) + (size_t)n0 * KD;

    float acc[32];
#pragma unroll
    for (int i = 0; i < 32; i++) acc[i] = 0.f;

    auto load_stage = [&](int st, int kb) {
        uint32_t base = sb0 + (uint32_t)(st * STAGEB);
#pragma unroll
        for (int mtx = 0; mtx < 2; mtx++) {
            const __nv_bfloat16* src = mtx ? Al : Ah;
#pragma unroll
            for (int it = 0; it < 2; it++) {
                int q = tid + it * 256;
                int row = q >> 2, g = q & 3;
                uint32_t dst = base + (uint32_t)(mtx * ALOFF + row * 64
                                                 + ((g ^ ((row >> 1) & 3)) << 4));
                CP_ASYNC16(dst, src + (size_t)row * KD + kb * BK + g * 8);
            }
        }
#pragma unroll
        for (int mtx = 0; mtx < 2; mtx++) {
            const __nv_bfloat16* src = mtx ? Wl : Wh;
            int row = tid >> 2, g = tid & 3;
            uint32_t dst = base + (uint32_t)(WOFF + mtx * 4096 + row * 64
                                             + ((g ^ ((row >> 1) & 3)) << 4));
            CP_ASYNC16(dst, src + (size_t)row * KD + kb * BK + g * 8);
        }
        CP_COMMIT();
    };

    load_stage(0, 0);
    load_stage(1, 1);
    for (int kb = 0; kb < NKB; kb++) {
        if (kb + 1 < NKB) CP_WAIT(1); else CP_WAIT(0);
        __syncthreads();
        if (kb + 2 < NKB) load_stage((kb + 2) % 3, kb + 2);
        uint32_t st = sb0 + (uint32_t)((kb % 3) * STAGEB);
#pragma unroll
        for (int ks = 0; ks < 2; ks++) {
            uint32_t afh[2][4], afl[2][4];
#pragma unroll
            for (int im = 0; im < 2; im++) {
                int row = warp_m * 32 + im * 16 + (lane & 7) + ((lane >> 3) & 1) * 8;
                int gc = ks * 2 + (lane >> 4);
                uint32_t sw = (uint32_t)(row * 64 + ((gc ^ ((row >> 1) & 3)) << 4));
                ldsm4(afh[im], st + AOFF + sw);
                ldsm4(afl[im], st + ALOFF + sw);
            }
#pragma unroll
            for (int jn2 = 0; jn2 < 2; jn2++) {
                uint32_t bfh[4], bfl[4];
                int rowb = warp_n * 32 + jn2 * 16 + (lane & 7) + (lane >> 4) * 8;
                int gcb = ks * 2 + ((lane >> 3) & 1);
                uint32_t swb = (uint32_t)(rowb * 64 + ((gcb ^ ((rowb >> 1) & 3)) << 4));
                ldsm4(bfh, st + WOFF + swb);
                ldsm4(bfl, st + WLOFF + swb);
#pragma unroll
                for (int im = 0; im < 2; im++) {
#pragma unroll
                    for (int na = 0; na < 2; na++) {
                        float* d = &acc[(im * 4 + jn2 * 2 + na) * 4];
                        mma16816(d, afh[im], bfh + na * 2);
                        mma16816(d, afh[im], bfl + na * 2);
                        mma16816(d, afl[im], bfh + na * 2);
                    }
                }
            }
        }
    }
    __syncthreads();

    float* Csm = (float*)dynsmem;
    {
        int r0 = warp_m * 32 + (lane >> 2);
        int c0 = warp_n * 32 + (lane & 3) * 2;
#pragma unroll
        for (int im = 0; im < 2; im++) {
#pragma unroll
            for (int jn = 0; jn < 4; jn++) {
                float* d = &acc[(im * 4 + jn) * 4];
                int rr = r0 + im * 16, cc = c0 + jn * 8;
                Csm[rr * 68 + cc] = d[0];
                Csm[rr * 68 + cc + 1] = d[1];
                Csm[(rr + 8) * 68 + cc] = d[2];
                Csm[(rr + 8) * 68 + cc + 1] = d[3];
            }
        }
    }
    __syncthreads();

    int sec = 0, h0 = 0;
    if (EPI == 1) { sec = n0 >> 9; h0 = (n0 & 511) >> 6; }
#pragma unroll 4
    for (int it = 0; it < 32; it++) {
        int idx = it * 256 + tid;
        int row = idx >> 6, col = idx & 63;
        float val = Csm[row * 68 + col] + bias[n0 + col];
        int m = m0 + row;
        if (EPI == 0) {
            g_out2[(size_t)m * Dm + n0 + col] = val;
        } else {
            int b = m >> 12, l = m & 4095;
            size_t rowoff = ((size_t)(b * Hh + h0) * Lq + l) * Ee + col;
            if (sec == 2) {
                g_v[rowoff] = val;
            } else {
                float cum = g_cum[(size_t)(b * Hh + h0) * Lq + l];
                float mul = (sec == 0) ? 0.125f * expf(cum) : expf(-cum);
                float fm = (val > 0.f) ? val + 1.f : expf(val);
                ((sec == 0) ? g_q : g_k)[rowoff] = fm * mul;
            }
        }
    }
}

// ---------------- K2: per-chunk S = KᵀV (64x64), z = Σk, cp.async pipeline ---
__global__ __launch_bounds__(256) void chunk_sum_kernel() {
    __shared__ __align__(16) float Ks[2][32 * Ee];
    __shared__ __align__(16) float Vs[2][32 * Ee];
    int blk = blockIdx.x;
    int c = blk & (NC - 1);
    int bh = blk >> 5;
    int tid = threadIdx.x;
    int tx = tid & 15, ty = tid >> 4;
    const float* Kb = g_k + ((size_t)bh * Lq + c * CS) * Ee;
    const float* Vb = g_v + ((size_t)bh * Lq + c * CS) * Ee;
    uint32_t ksb = smem_u32(Ks), vsb = smem_u32(Vs);

    auto prefetch = [&](int st, int r0) {
#pragma unroll
        for (int u = 0; u < 2; u++) {
            int idx = tid + u * 256;                 // 0..511 float4
            CP_ASYNC16(ksb + (uint32_t)(st * 8192 + idx * 16),
                       (const float4*)(Kb + r0 * Ee) + idx);
            CP_ASYNC16(vsb + (uint32_t)(st * 8192 + idx * 16),
                       (const float4*)(Vb + r0 * Ee) + idx);
        }
        CP_COMMIT();
    };
    prefetch(0, 0);

    float acc[4][4];
#pragma unroll
    for (int i = 0; i < 4; i++)
#pragma unroll
        for (int j = 0; j < 4; j++) acc[i][j] = 0.f;
    float zacc[4] = {0.f, 0.f, 0.f, 0.f};

    for (int t0 = 0; t0 < 4; t0++) {
        CP_WAIT(0);
        __syncthreads();
        if (t0 + 1 < 4) prefetch((t0 + 1) & 1, (t0 + 1) * 32);
        const float* Kt = Ks[t0 & 1];
        const float* Vt = Vs[t0 & 1];
#pragma unroll
        for (int r = 0; r < 32; r++) {
            float a[4], bq[4];
#pragma unroll
            for (int i = 0; i < 4; i++) a[i] = Kt[r * Ee + ty * 4 + i];
#pragma unroll
            for (int j = 0; j < 4; j++) bq[j] = Vt[r * Ee + tx * 4 + j];
#pragma unroll
            for (int i = 0; i < 4; i++) {
                zacc[i] += a[i];
#pragma unroll
                for (int j = 0; j < 4; j++) acc[i][j] += a[i] * bq[j];
            }
        }
    }
    float* Sd = g_S + (size_t)blk * Ee * Ee;
#pragma unroll
    for (int i = 0; i < 4; i++)
#pragma unroll
        for (int j = 0; j < 4; j++) Sd[(ty * 4 + i) * Ee + tx * 4 + j] = acc[i][j];
    if (tx == 0) {
        float* zd = g_z + (size_t)blk * Ee;
#pragma unroll
        for (int i = 0; i < 4; i++) zd[ty * 4 + i] = zacc[i];
    }
}

// ---------------- K3: exclusive prefix over chunks (full-width grid) ---------
__global__ __launch_bounds__(512) void chunk_prefix_kernel() {
    int bh = blockIdx.x;
    int idx = blockIdx.y * 512 + threadIdx.x;
    float* p = g_S + (size_t)bh * NC * (Ee * Ee) + idx;
    float v[NC];
#pragma unroll
    for (int c = 0; c < NC; c++) v[c] = p[(size_t)c * (Ee * Ee)];
    float carry = 0.f;
#pragma unroll
    for (int c = 0; c < NC; c++) { p[(size_t)c * (Ee * Ee)] = carry; carry += v[c]; }
    if (blockIdx.y == 0 && threadIdx.x < Ee) {
        float* pz = g_z + (size_t)bh * NC * Ee + threadIdx.x;
        float zv[NC];
#pragma unroll
        for (int c = 0; c < NC; c++) zv[c] = pz[c * Ee];
        float zc = 0.f;
#pragma unroll
        for (int c = 0; c < NC; c++) { pz[c * Ee] = zc; zc += zv[c]; }
    }
}

// ---------------- K4: chunked causal linear attention, f-split pairs ---------
// 256 threads: warp w covers rows w*16..w*16+15, lane>>4 selects feature half.
__global__ __launch_bounds__(256, 3) void attn_kernel() {
    __shared__ float sS[Ee * Ee];                    // 16 KB
    __shared__ float sz[Ee];
    __shared__ __align__(16) float sK[2][32 * Ee];   // 8 KB x2
    __shared__ __align__(16) float sV[2][32 * Ee];
    int blk = blockIdx.x;
    int c = blk & 31;
    int bh = blk >> 5;
    int tid = threadIdx.x;
    int wid = tid >> 5, lane = tid & 31;
    int row = wid * 16 + (lane & 15);
    int fb = (lane >> 4) << 5;                       // 0 or 32
    const float* Kb = g_k + ((size_t)bh * Lq + c * CS) * Ee;
    const float* Vb = g_v + ((size_t)bh * Lq + c * CS) * Ee;
    uint32_t ksb = smem_u32(sK), vsb = smem_u32(sV);
    uint32_t ssb = smem_u32(sS), szb = smem_u32(sz);

    auto prefetch = [&](int st, int s0) {
#pragma unroll
        for (int u = 0; u < 2; u++) {
            int idx = tid + u * 256;
            CP_ASYNC16(ksb + (uint32_t)(st * 8192 + idx * 16),
                       (const float4*)(Kb + s0 * Ee) + idx);
            CP_ASYNC16(vsb + (uint32_t)(st * 8192 + idx * 16),
                       (const float4*)(Vb + s0 * Ee) + idx);
        }
    };
    // tile 0 + S + z in the first async group
    prefetch(0, 0);
    {
        const float4* Sp = (const float4*)(g_S + (size_t)blk * (Ee * Ee));
#pragma unroll
        for (int u = 0; u < 4; u++)
            CP_ASYNC16(ssb + (uint32_t)((tid + u * 256) * 16), Sp + tid + u * 256);
        if (tid < 16)
            CP_ASYNC16(szb + (uint32_t)(tid * 16), (const float4*)(g_z + (size_t)blk * Ee) + tid);
    }
    CP_COMMIT();

    // q own half
    const float* qp = g_q + ((size_t)bh * Lq + c * CS + row) * Ee + fb;
    float q[32];
#pragma unroll
    for (int i = 0; i < 8; i++) {
        float4 v4 = ((const float4*)qp)[i];
        q[4 * i] = v4.x; q[4 * i + 1] = v4.y; q[4 * i + 2] = v4.z; q[4 * i + 3] = v4.w;
    }
    float num[32];
#pragma unroll
    for (int j = 0; j < 32; j++) num[j] = 0.f;
    float den = 0.f;

    // ---- intra-chunk: 4 K/V tiles of 32 rows, double-buffered ----
    int row_max = wid * 16 + 15;
    for (int t0 = 0; t0 < 4; t0++) {
        CP_WAIT(0);
        __syncthreads();
        if (t0 + 1 < 4) { prefetch((t0 + 1) & 1, (t0 + 1) * 32); CP_COMMIT(); }
        if (t0 * 32 <= row_max) {
            const float* Kt = sK[t0 & 1];
            const float* Vt = sV[t0 & 1];
#pragma unroll 4
            for (int s = 0; s < 32; s++) {
                const float4* kr = (const float4*)(Kt + s * Ee + fb);
                float ap = 0.f;
#pragma unroll
                for (int i4 = 0; i4 < 8; i4++) {
                    float4 kv = kr[i4];
                    ap += q[4 * i4] * kv.x + q[4 * i4 + 1] * kv.y
                        + q[4 * i4 + 2] * kv.z + q[4 * i4 + 3] * kv.w;
                }
                float a = ap + __shfl_xor_sync(0xffffffffu, ap, 16);
                if (t0 * 32 + s <= row) {
                    den += a;
                    const float4* vr = (const float4*)(Vt + s * Ee + fb);
#pragma unroll
                    for (int j4 = 0; j4 < 8; j4++) {
                        float4 vv = vr[j4];
                        num[4 * j4]     += a * vv.x;
                        num[4 * j4 + 1] += a * vv.y;
                        num[4 * j4 + 2] += a * vv.z;
                        num[4 * j4 + 3] += a * vv.w;
                    }
                }
            }
        }
    }

    // ---- inter-chunk: num += q . S_prev ; den += q . z_prev (pair-split) ----
    {
        float dp = 0.f;
#pragma unroll
        for (int i = 0; i < 32; i++) dp += q[i] * sz[fb + i];
        den += 1e-6f + dp + __shfl_xor_sync(0xffffffffu, dp, 16);
        int ofb = fb ^ 32;
#pragma unroll
        for (int jc = 0; jc < 4; jc++) {
            float own[8], oth[8];
#pragma unroll
            for (int j = 0; j < 8; j++) { own[j] = 0.f; oth[j] = 0.f; }
#pragma unroll
            for (int i = 0; i < 32; i++) {
                float qe = q[i];
                const float* srow = sS + (fb + i) * Ee;
                const float4* so = (const float4*)(srow + fb + jc * 8);
                const float4* sx = (const float4*)(srow + ofb + jc * 8);
                float4 a0 = so[0], a1 = so[1];
                float4 b0 = sx[0], b1 = sx[1];
                own[0] += qe * a0.x; own[1] += qe * a0.y; own[2] += qe * a0.z; own[3] += qe * a0.w;
                own[4] += qe * a1.x; own[5] += qe * a1.y; own[6] += qe * a1.z; own[7] += qe * a1.w;
                oth[0] += qe * b0.x; oth[1] += qe * b0.y; oth[2] += qe * b0.z; oth[3] += qe * b0.w;
                oth[4] += qe * b1.x; oth[5] += qe * b1.y; oth[6] += qe * b1.z; oth[7] += qe * b1.w;
            }
#pragma unroll
            for (int j = 0; j < 8; j++)
                num[jc * 8 + j] += own[j] + __shfl_xor_sync(0xffffffffu, oth[j], 16);
        }
    }

    float invd = 1.0f / den;
    int b = bh >> 3, h = bh & 7;
    size_t off = ((size_t)(b * Lq + c * CS + row)) * Dm + h * Ee + fb;
    __nv_bfloat162* oh = (__nv_bfloat162*)(g_ahi + off);
    __nv_bfloat162* ol = (__nv_bfloat162*)(g_alo + off);
#pragma unroll
    for (int f2 = 0; f2 < 16; f2++) {
        float v0 = num[2 * f2] * invd, v1 = num[2 * f2 + 1] * invd;
        __nv_bfloat162 ph, pl;
        split2(v0, v1, ph, pl);
        oh[f2] = ph; ol[f2] = pl;
    }
}

// ---------------- K6: RMSNorm -------------------------------------------------
__global__ void rmsnorm_kernel(const float* __restrict__ scale, float* __restrict__ out) {
    int row = blockIdx.x;
    int tid = threadIdx.x;
    const float* r = g_out2 + (size_t)row * Dm;
    float v0 = r[tid], v1 = r[tid + 256];
    float ss = v0 * v0 + v1 * v1;
#pragma unroll
    for (int o = 16; o; o >>= 1) ss += __shfl_xor_sync(0xffffffffu, ss, o);
    __shared__ float wsum[8];
    __shared__ float rn_s;
    if ((tid & 31) == 0) wsum[tid >> 5] = ss;
    __syncthreads();
    if (tid == 0) {
        float tt = 0.f;
#pragma unroll
        for (int i = 0; i < 8; i++) tt += wsum[i];
        rn_s = rsqrtf(tt * (1.0f / 512.0f) + 1e-8f);
    }
    __syncthreads();
    float rn = rn_s;
    out[(size_t)row * Dm + tid] = v0 * rn * scale[tid];
    out[(size_t)row * Dm + tid + 256] = v1 * rn * scale[tid + 256];
}

// ---------------- launch ------------------------------------------------------
extern "C" void kernel_launch(void* const* d_in, const int* in_sizes, int n_in,
                              void* d_out, int out_size) {
    const float* x          = (const float*)d_in[0];
    const float* qkv_w      = (const float*)d_in[1];
    const float* qkv_b      = (const float*)d_in[2];
    const float* out_w      = (const float*)d_in[3];
    const float* out_b      = (const float*)d_in[4];
    const float* decay_w    = (const float*)d_in[5];
    const float* decay_b    = (const float*)d_in[6];
    const float* norm_scale = (const float*)d_in[7];
    float* out = (float*)d_out;
    (void)in_sizes; (void)n_in; (void)out_size;

    const int DYN = 73728;
    static bool attr_set = false;
    if (!attr_set) {
        cudaFuncSetAttribute(gemm_mma_kernel<1>, cudaFuncAttributeMaxDynamicSharedMemorySize, DYN);
        cudaFuncSetAttribute(gemm_mma_kernel<0>, cudaFuncAttributeMaxDynamicSharedMemorySize, DYN);
        attr_set = true;
    }

    split_w_kernel<<<1024, 256>>>(qkv_w, out_w);
    split_x_decay_kernel<<<1024, 256>>>(x, decay_w, decay_b);
    cum_scan_kernel<<<BHn, 512>>>();

    gemm_mma_kernel<1><<<dim3(24, 64), 256, DYN>>>(qkv_b);

    chunk_sum_kernel<<<BHn * NC, 256>>>();
    chunk_prefix_kernel<<<dim3(BHn, 8), 512>>>();
    attn_kernel<<<BHn * NC, 256>>>();

    gemm_mma_kernel<0><<<dim3(8, 64), 256, DYN>>>(out_b);

    rmsnorm_kernel<<<Bsz * Lq, 256>>>(norm_scale, out);
}

// round 11
// speedup vs baseline: 1.3226x; 1.3226x over previous
#include <cuda_runtime.h>
#include <cuda_fp16.h>
#include <cstdint>

#define Bsz 2
#define Lq 4096
#define Dm 512
#define Hh 8
#define Ee 64
#define NC 32
#define CS 128
#define BHn (Bsz*Hh)

// ---------------- scratch ----------------------------------------------------
__device__ float g_loglam[BHn * Lq];
__device__ float g_cum[BHn * Lq];
__device__ float g_q[BHn * Lq * Ee];
__device__ float g_k[BHn * Lq * Ee];
__device__ float g_v[BHn * Lq * Ee];
__device__ float g_S[BHn * NC * Ee * Ee];
__device__ float g_z[BHn * NC * Ee];
__device__ float g_out2[Bsz * Lq * Dm];
__device__ __align__(16) __half g_x16[Bsz * Lq * Dm];
__device__ __align__(16) __half g_a16[Bsz * Lq * Dm];
__device__ __align__(16) __half g_wq_hi[3 * Dm * Dm];
__device__ __align__(16) __half g_wq_lo[3 * Dm * Dm];
__device__ __align__(16) __half g_wo_hi[Dm * Dm];
__device__ __align__(16) __half g_wo_lo[Dm * Dm];

// ---------------- low-level helpers -------------------------------------------
__device__ __forceinline__ uint32_t smem_u32(const void* p) {
    uint32_t a;
    asm("{ .reg .u64 t; cvta.to.shared.u64 t, %1; cvt.u32.u64 %0, t; }" : "=r"(a) : "l"(p));
    return a;
}
__device__ __forceinline__ void ldsm4(uint32_t* r, uint32_t addr) {
    asm volatile("ldmatrix.sync.aligned.m8n8.x4.shared.b16 {%0,%1,%2,%3}, [%4];"
                 : "=r"(r[0]), "=r"(r[1]), "=r"(r[2]), "=r"(r[3]) : "r"(addr));
}
__device__ __forceinline__ void mma16816h(float* d, const uint32_t* a, const uint32_t* b) {
    asm volatile("mma.sync.aligned.m16n8k16.row.col.f32.f16.f16.f32 "
                 "{%0,%1,%2,%3}, {%4,%5,%6,%7}, {%8,%9}, {%0,%1,%2,%3};"
                 : "+f"(d[0]), "+f"(d[1]), "+f"(d[2]), "+f"(d[3])
                 : "r"(a[0]), "r"(a[1]), "r"(a[2]), "r"(a[3]), "r"(b[0]), "r"(b[1]));
}
#define CP_ASYNC16(sm, gm) \
    asm volatile("cp.async.cg.shared.global [%0], [%1], 16;" :: "r"(sm), "l"(gm))
#define CP_COMMIT() asm volatile("cp.async.commit_group;" ::: "memory")
#define CP_WAIT(n)  asm volatile("cp.async.wait_group %0;" :: "n"(n) : "memory")

__device__ __forceinline__ void splitw(float v0, float v1, __half2& ph, __half2& pl) {
    __half h0 = __float2half(v0), h1 = __float2half(v1);
    ph = __halves2half2(h0, h1);
    pl = __halves2half2(__float2half(v0 - __half2float(h0)),
                        __float2half(v1 - __half2float(h1)));
}

// ---------------- K0: fused x->fp16 + decay logits (one pass over x) ---------
__global__ __launch_bounds__(256) void split_x_decay_kernel(const float* __restrict__ x,
                                                            const float* __restrict__ dw,
                                                            const float* __restrict__ db) {
    int warp = (blockIdx.x * blockDim.x + threadIdx.x) >> 5;   // 0..8191 row
    int lane = threadIdx.x & 31;
    const float4* xr = (const float4*)(x + (size_t)warp * Dm);
    float4 xv[4];
#pragma unroll
    for (int i = 0; i < 4; i++) xv[i] = xr[lane + 32 * i];
    __half2* xo = (__half2*)(g_x16 + (size_t)warp * Dm);
#pragma unroll
    for (int i = 0; i < 4; i++) {
        int idx = lane + 32 * i;
        xo[2 * idx]     = __floats2half2_rn(xv[i].x, xv[i].y);
        xo[2 * idx + 1] = __floats2half2_rn(xv[i].z, xv[i].w);
    }
    int b = warp >> 12, l = warp & 4095;
#pragma unroll
    for (int h = 0; h < Hh; h++) {
        const float4* wr = (const float4*)(dw + (size_t)h * Dm);
        float p = 0.f;
#pragma unroll
        for (int i = 0; i < 4; i++) {
            float4 w = wr[lane + 32 * i];
            p += xv[i].x * w.x + xv[i].y * w.y + xv[i].z * w.z + xv[i].w * w.w;
        }
#pragma unroll
        for (int o = 16; o; o >>= 1) p += __shfl_xor_sync(0xffffffffu, p, o);
        if (lane == 0) {
            float logit = p + db[h];
            float lam = 0.9f + 0.1f / (1.f + expf(-logit));
            lam = fmaxf(lam, 1e-6f);
            g_loglam[((size_t)(b * Hh + h)) * Lq + l] = logf(lam);
        }
    }
}

// ---------------- K0w: both weight splits (fp16 hi/lo) in one launch ---------
__global__ void split_w_kernel(const float* __restrict__ qkv_w,
                               const float* __restrict__ out_w) {
    int i = blockIdx.x * blockDim.x + threadIdx.x;
    const int nq = 3 * Dm * Dm / 4;
    const float* s; __half *hi, *lo; int j;
    if (i < nq) { s = qkv_w; hi = g_wq_hi; lo = g_wq_lo; j = i; }
    else {
        j = i - nq;
        if (j >= Dm * Dm / 4) return;
        s = out_w; hi = g_wo_hi; lo = g_wo_lo;
    }
    float4 v = ((const float4*)s)[j];
    __half2 ph0, pl0, ph1, pl1;
    splitw(v.x, v.y, ph0, pl0);
    splitw(v.z, v.w, ph1, pl1);
    ((__half2*)hi)[2 * j] = ph0; ((__half2*)hi)[2 * j + 1] = ph1;
    ((__half2*)lo)[2 * j] = pl0; ((__half2*)lo)[2 * j + 1] = pl1;
}

// ---------------- K0b: inclusive scan of log lambda per (b,h), clip ----------
__global__ void cum_scan_kernel() {
    int bh = blockIdx.x;
    int tid = threadIdx.x;
    int lane = tid & 31, w = tid >> 5;
    const float* src = g_loglam + (size_t)bh * Lq + tid * 8;
    float v[8]; float s = 0.f;
#pragma unroll
    for (int j = 0; j < 8; j++) { v[j] = src[j]; s += v[j]; }
    float sc = s;
#pragma unroll
    for (int o = 1; o < 32; o <<= 1) {
        float n = __shfl_up_sync(0xffffffffu, sc, o);
        if (lane >= o) sc += n;
    }
    __shared__ float wt[16];
    if (lane == 31) wt[w] = sc;
    __syncthreads();
    if (tid < 16) {
        float ws = wt[tid];
#pragma unroll
        for (int o = 1; o < 16; o <<= 1) {
            float n = __shfl_up_sync(0xffffu, ws, o);
            if (tid >= o) ws += n;
        }
        wt[tid] = ws;
    }
    __syncthreads();
    float base = ((w > 0) ? wt[w - 1] : 0.f) + sc - s;
    float run = base;
    float* dst = g_cum + (size_t)bh * Lq + tid * 8;
#pragma unroll
    for (int j = 0; j < 8; j++) {
        run += v[j];
        dst[j] = fminf(fmaxf(run, -50.f), 50.f);
    }
}

// ---------------- HMMA GEMM fp16: C = A·(Wh+Wl)^T, 128x64 tile, occ 3 --------
// smem per stage: A(8K) Wh(4K) Wl(4K) = 16 KB; 3 stages = 48 KB
template <int EPI>
__global__ __launch_bounds__(256, 3) void gemm_mma_kernel(const float* __restrict__ bias) {
    extern __shared__ __align__(16) char dynsmem[];
    constexpr int KD = 512, BK = 32, NKB = KD / BK;
    constexpr int WOFF = 8192, WLOFF = 12288;
    constexpr int STAGEB = 16384;
    uint32_t sb0 = smem_u32(dynsmem);

    int tid = threadIdx.x;
    int warp = tid >> 5, lane = tid & 31;
    int warp_m = warp & 3, warp_n = warp >> 2;        // 4 x 2, warp tile 32m x 32n
    int m0 = blockIdx.y * 128, n0 = blockIdx.x * 64;

    const __half* A  = (EPI ? g_x16 : g_a16) + (size_t)m0 * KD;
    const __half* Wh = (EPI ? g_wq_hi : g_wo_hi) + (size_t)n0 * KD;
    const __half* Wl = (EPI ? g_wq_lo : g_wo_lo) + (size_t)n0 * KD;

    float acc[32];
#pragma unroll
    for (int i = 0; i < 32; i++) acc[i] = 0.f;

    auto load_stage = [&](int st, int kb) {
        uint32_t base = sb0 + (uint32_t)(st * STAGEB);
#pragma unroll
        for (int it = 0; it < 2; it++) {
            int q = tid + it * 256;                  // 0..511
            int row = q >> 2, g = q & 3;
            uint32_t dst = base + (uint32_t)(row * 64 + ((g ^ ((row >> 1) & 3)) << 4));
            CP_ASYNC16(dst, A + (size_t)row * KD + kb * BK + g * 8);
        }
        {
            int row = tid >> 2, g = tid & 3;         // 256 granules each
            uint32_t sw = (uint32_t)(row * 64 + ((g ^ ((row >> 1) & 3)) << 4));
            CP_ASYNC16(base + WOFF + sw, Wh + (size_t)row * KD + kb * BK + g * 8);
            CP_ASYNC16(base + WLOFF + sw, Wl + (size_t)row * KD + kb * BK + g * 8);
        }
        CP_COMMIT();
    };

    load_stage(0, 0);
    load_stage(1, 1);
    for (int kb = 0; kb < NKB; kb++) {
        if (kb + 1 < NKB) CP_WAIT(1); else CP_WAIT(0);
        __syncthreads();
        if (kb + 2 < NKB) load_stage((kb + 2) % 3, kb + 2);
        uint32_t st = sb0 + (uint32_t)((kb % 3) * STAGEB);
#pragma unroll
        for (int ks = 0; ks < 2; ks++) {
            uint32_t af[2][4];
#pragma unroll
            for (int im = 0; im < 2; im++) {
                int row = warp_m * 32 + im * 16 + (lane & 7) + ((lane >> 3) & 1) * 8;
                int gc = ks * 2 + (lane >> 4);
                uint32_t sw = (uint32_t)(row * 64 + ((gc ^ ((row >> 1) & 3)) << 4));
                ldsm4(af[im], st + sw);
            }
#pragma unroll
            for (int jn2 = 0; jn2 < 2; jn2++) {
                uint32_t bfh[4], bfl[4];
                int rowb = warp_n * 32 + jn2 * 16 + (lane & 7) + (lane >> 4) * 8;
                int gcb = ks * 2 + ((lane >> 3) & 1);
                uint32_t swb = (uint32_t)(rowb * 64 + ((gcb ^ ((rowb >> 1) & 3)) << 4));
                ldsm4(bfh, st + WOFF + swb);
                ldsm4(bfl, st + WLOFF + swb);
#pragma unroll
                for (int im = 0; im < 2; im++) {
#pragma unroll
                    for (int na = 0; na < 2; na++) {
                        float* d = &acc[(im * 4 + jn2 * 2 + na) * 4];
                        mma16816h(d, af[im], bfh + na * 2);
                        mma16816h(d, af[im], bfl + na * 2);
                    }
                }
            }
        }
    }
    __syncthreads();

    float* Csm = (float*)dynsmem;                     // 128x68 fp32 = 34.8 KB
    {
        int r0 = warp_m * 32 + (lane >> 2);
        int c0 = warp_n * 32 + (lane & 3) * 2;
#pragma unroll
        for (int im = 0; im < 2; im++) {
#pragma unroll
            for (int jn = 0; jn < 4; jn++) {
                float* d = &acc[(im * 4 + jn) * 4];
                int rr = r0 + im * 16, cc = c0 + jn * 8;
                Csm[rr * 68 + cc] = d[0];
                Csm[rr * 68 + cc + 1] = d[1];
                Csm[(rr + 8) * 68 + cc] = d[2];
                Csm[(rr + 8) * 68 + cc + 1] = d[3];
            }
        }
    }
    __syncthreads();

    int sec = 0, h0 = 0;
    if (EPI == 1) { sec = n0 >> 9; h0 = (n0 & 511) >> 6; }
#pragma unroll 4
    for (int it = 0; it < 32; it++) {
        int idx = it * 256 + tid;
        int row = idx >> 6, col = idx & 63;
        float val = Csm[row * 68 + col] + bias[n0 + col];
        int m = m0 + row;
        if (EPI == 0) {
            g_out2[(size_t)m * Dm + n0 + col] = val;
        } else {
            int b = m >> 12, l = m & 4095;
            size_t rowoff = ((size_t)(b * Hh + h0) * Lq + l) * Ee + col;
            if (sec == 2) {
                g_v[rowoff] = val;
            } else {
                float cum = g_cum[(size_t)(b * Hh + h0) * Lq + l];
                float mul = (sec == 0) ? 0.125f * expf(cum) : expf(-cum);
                float fm = (val > 0.f) ? val + 1.f : expf(val);
                ((sec == 0) ? g_q : g_k)[rowoff] = fm * mul;
            }
        }
    }
}

// ---------------- K2: per-chunk S = KᵀV (64x64), z = Σk, cp.async pipeline ---
__global__ __launch_bounds__(256) void chunk_sum_kernel() {
    __shared__ __align__(16) float Ks[2][32 * Ee];
    __shared__ __align__(16) float Vs[2][32 * Ee];
    int blk = blockIdx.x;
    int c = blk & (NC - 1);
    int bh = blk >> 5;
    int tid = threadIdx.x;
    int tx = tid & 15, ty = tid >> 4;
    const float* Kb = g_k + ((size_t)bh * Lq + c * CS) * Ee;
    const float* Vb = g_v + ((size_t)bh * Lq + c * CS) * Ee;
    uint32_t ksb = smem_u32(Ks), vsb = smem_u32(Vs);

    auto prefetch = [&](int st, int r0) {
#pragma unroll
        for (int u = 0; u < 2; u++) {
            int idx = tid + u * 256;
            CP_ASYNC16(ksb + (uint32_t)(st * 8192 + idx * 16),
                       (const float4*)(Kb + r0 * Ee) + idx);
            CP_ASYNC16(vsb + (uint32_t)(st * 8192 + idx * 16),
                       (const float4*)(Vb + r0 * Ee) + idx);
        }
        CP_COMMIT();
    };
    prefetch(0, 0);

    float acc[4][4];
#pragma unroll
    for (int i = 0; i < 4; i++)
#pragma unroll
        for (int j = 0; j < 4; j++) acc[i][j] = 0.f;
    float zacc[4] = {0.f, 0.f, 0.f, 0.f};

    for (int t0 = 0; t0 < 4; t0++) {
        CP_WAIT(0);
        __syncthreads();
        if (t0 + 1 < 4) prefetch((t0 + 1) & 1, (t0 + 1) * 32);
        const float* Kt = Ks[t0 & 1];
        const float* Vt = Vs[t0 & 1];
#pragma unroll
        for (int r = 0; r < 32; r++) {
            float a[4], bq[4];
#pragma unroll
            for (int i = 0; i < 4; i++) a[i] = Kt[r * Ee + ty * 4 + i];
#pragma unroll
            for (int j = 0; j < 4; j++) bq[j] = Vt[r * Ee + tx * 4 + j];
#pragma unroll
            for (int i = 0; i < 4; i++) {
                zacc[i] += a[i];
#pragma unroll
                for (int j = 0; j < 4; j++) acc[i][j] += a[i] * bq[j];
            }
        }
    }
    float* Sd = g_S + (size_t)blk * Ee * Ee;
#pragma unroll
    for (int i = 0; i < 4; i++)
#pragma unroll
        for (int j = 0; j < 4; j++) Sd[(ty * 4 + i) * Ee + tx * 4 + j] = acc[i][j];
    if (tx == 0) {
        float* zd = g_z + (size_t)blk * Ee;
#pragma unroll
        for (int i = 0; i < 4; i++) zd[ty * 4 + i] = zacc[i];
    }
}

// ---------------- K3: exclusive prefix over chunks (full-width grid) ---------
__global__ __launch_bounds__(512) void chunk_prefix_kernel() {
    int bh = blockIdx.x;
    int idx = blockIdx.y * 512 + threadIdx.x;
    float* p = g_S + (size_t)bh * NC * (Ee * Ee) + idx;
    float v[NC];
#pragma unroll
    for (int c = 0; c < NC; c++) v[c] = p[(size_t)c * (Ee * Ee)];
    float carry = 0.f;
#pragma unroll
    for (int c = 0; c < NC; c++) { p[(size_t)c * (Ee * Ee)] = carry; carry += v[c]; }
    if (blockIdx.y == 0 && threadIdx.x < Ee) {
        float* pz = g_z + (size_t)bh * NC * Ee + threadIdx.x;
        float zv[NC];
#pragma unroll
        for (int c = 0; c < NC; c++) zv[c] = pz[c * Ee];
        float zc = 0.f;
#pragma unroll
        for (int c = 0; c < NC; c++) { pz[c * Ee] = zc; zc += zv[c]; }
    }
}

// ---------------- K4: chunked causal linear attention (R8 form, fp16 out) ----
__global__ __launch_bounds__(128) void attn_kernel() {
    __shared__ float sh[Ee * Ee + Ee];
    int blk = blockIdx.x;
    int c = blk & 31;
    int bh = blk >> 5;
    int t = threadIdx.x;
    const float* qp = g_q + ((size_t)bh * Lq + c * CS + t) * Ee;
    float q[Ee];
#pragma unroll
    for (int i = 0; i < 16; i++) {
        float4 v4 = ((const float4*)qp)[i];
        q[4 * i] = v4.x; q[4 * i + 1] = v4.y; q[4 * i + 2] = v4.z; q[4 * i + 3] = v4.w;
    }
    const float* Sp = g_S + (size_t)blk * Ee * Ee;
#pragma unroll
    for (int u = 0; u < 8; u++) ((float4*)sh)[t + u * 128] = ((const float4*)Sp)[t + u * 128];
    if (t < 16) ((float4*)(sh + Ee * Ee))[t] = ((const float4*)(g_z + (size_t)blk * Ee))[t];
    __syncthreads();

    float num[Ee];
#pragma unroll
    for (int f = 0; f < Ee; f++) num[f] = 0.f;
    float den = 1e-6f;
#pragma unroll
    for (int e = 0; e < Ee; e++) {
        float qe = q[e];
        den += qe * sh[Ee * Ee + e];
        const float4* srow = (const float4*)(sh + e * Ee);
#pragma unroll
        for (int f4 = 0; f4 < 16; f4++) {
            float4 sv = srow[f4];
            num[4 * f4]     += qe * sv.x;
            num[4 * f4 + 1] += qe * sv.y;
            num[4 * f4 + 2] += qe * sv.z;
            num[4 * f4 + 3] += qe * sv.w;
        }
    }
    __syncthreads();

    const float* Kb = g_k + ((size_t)bh * Lq + c * CS) * Ee;
    const float* Vb = g_v + ((size_t)bh * Lq + c * CS) * Ee;
    for (int s0 = 0; s0 < CS; s0 += 32) {
#pragma unroll
        for (int u = 0; u < 4; u++) {
            int idx = t + u * 128;
            ((float4*)sh)[idx] = ((const float4*)(Kb + s0 * Ee))[idx];
            ((float4*)(sh + 2048))[idx] = ((const float4*)(Vb + s0 * Ee))[idx];
        }
        __syncthreads();
        for (int s = 0; s < 32; s++) {
            if (s0 + s <= t) {
                float a = 0.f;
                const float4* krow = (const float4*)(sh + s * Ee);
#pragma unroll
                for (int e4 = 0; e4 < 16; e4++) {
                    float4 kv = krow[e4];
                    a += q[4 * e4] * kv.x + q[4 * e4 + 1] * kv.y
                       + q[4 * e4 + 2] * kv.z + q[4 * e4 + 3] * kv.w;
                }
                den += a;
                const float4* vrow = (const float4*)(sh + 2048 + s * Ee);
#pragma unroll
                for (int f4 = 0; f4 < 16; f4++) {
                    float4 vv = vrow[f4];
                    num[4 * f4]     += a * vv.x;
                    num[4 * f4 + 1] += a * vv.y;
                    num[4 * f4 + 2] += a * vv.z;
                    num[4 * f4 + 3] += a * vv.w;
                }
            }
        }
        __syncthreads();
    }
    float invd = 1.0f / den;
    int b = bh >> 3, h = bh & 7;
    size_t off = ((size_t)(b * Lq + c * CS + t)) * Dm + h * Ee;
    __half2* oh = (__half2*)(g_a16 + off);
#pragma unroll
    for (int f2 = 0; f2 < 32; f2++)
        oh[f2] = __floats2half2_rn(num[2 * f2] * invd, num[2 * f2 + 1] * invd);
}

// ---------------- K6: RMSNorm -------------------------------------------------
__global__ void rmsnorm_kernel(const float* __restrict__ scale, float* __restrict__ out) {
    int row = blockIdx.x;
    int tid = threadIdx.x;
    const float* r = g_out2 + (size_t)row * Dm;
    float v0 = r[tid], v1 = r[tid + 256];
    float ss = v0 * v0 + v1 * v1;
#pragma unroll
    for (int o = 16; o; o >>= 1) ss += __shfl_xor_sync(0xffffffffu, ss, o);
    __shared__ float wsum[8];
    __shared__ float rn_s;
    if ((tid & 31) == 0) wsum[tid >> 5] = ss;
    __syncthreads();
    if (tid == 0) {
        float tt = 0.f;
#pragma unroll
        for (int i = 0; i < 8; i++) tt += wsum[i];
        rn_s = rsqrtf(tt * (1.0f / 512.0f) + 1e-8f);
    }
    __syncthreads();
    float rn = rn_s;
    out[(size_t)row * Dm + tid] = v0 * rn * scale[tid];
    out[(size_t)row * Dm + tid + 256] = v1 * rn * scale[tid + 256];
}

// ---------------- launch ------------------------------------------------------
extern "C" void kernel_launch(void* const* d_in, const int* in_sizes, int n_in,
                              void* d_out, int out_size) {
    const float* x          = (const float*)d_in[0];
    const float* qkv_w      = (const float*)d_in[1];
    const float* qkv_b      = (const float*)d_in[2];
    const float* out_w      = (const float*)d_in[3];
    const float* out_b      = (const float*)d_in[4];
    const float* decay_w    = (const float*)d_in[5];
    const float* decay_b    = (const float*)d_in[6];
    const float* norm_scale = (const float*)d_in[7];
    float* out = (float*)d_out;
    (void)in_sizes; (void)n_in; (void)out_size;

    // dynamic smem: max(3 stages x 16 KB = 49152, C staging 34816)
    const int DYN = 49152;
    static bool attr_set = false;
    if (!attr_set) {
        cudaFuncSetAttribute(gemm_mma_kernel<1>, cudaFuncAttributeMaxDynamicSharedMemorySize, DYN);
        cudaFuncSetAttribute(gemm_mma_kernel<0>, cudaFuncAttributeMaxDynamicSharedMemorySize, DYN);
        attr_set = true;
    }

    split_w_kernel<<<1024, 256>>>(qkv_w, out_w);
    split_x_decay_kernel<<<1024, 256>>>(x, decay_w, decay_b);
    cum_scan_kernel<<<BHn, 512>>>();

    gemm_mma_kernel<1><<<dim3(24, 64), 256, DYN>>>(qkv_b);

    chunk_sum_kernel<<<BHn * NC, 256>>>();
    chunk_prefix_kernel<<<dim3(BHn, 8), 512>>>();
    attn_kernel<<<BHn * NC, 128>>>();

    gemm_mma_kernel<0><<<dim3(8, 64), 256, DYN>>>(out_b);

    rmsnorm_kernel<<<Bsz * Lq, 256>>>(norm_scale, out);
}